// round 15
// baseline (speedup 1.0000x reference)
#include <cuda_runtime.h>
#include <math.h>
#include <stdint.h>

#define BATCH 64
#define C 128
#define HW 1024
#define OUTC 640
#define REG_STRIDE (C*HW)
#define OUT_BSTRIDE (OUTC*HW)

#define KPAIR 1152            // per edge: 64 ci-pairs * 18 taps
#define NST_EDGE 36           // super-tiles (32 pairs = 64 k) per edge
#define NTILES 72             // 2 edges
#define TILE_BYTES 16384      // A super-tile: 128 co x 64 k fp16 = 128B rows
#define BTILE_BYTES 32768     // B super-tile: 256 px x 64 k fp16 = 128B rows
#define BUF_STRIDE (TILE_BYTES + BTILE_BYTES)   // 49152
#define PLANE 432             // pair-plane: 12 rows * 36 cols (f16x2 per px)
#define RING_SLOTS 9
#define RING_BYTES (RING_SLOTS*PLANE*4)         // 15552
#define OFF_STAGE (2*BUF_STRIDE)                // 98304
#define DSMEM_SZ  (OFF_STAGE + RING_BYTES + 1024)   // 114880
#define DSMEM_PRE (2*BUF_STRIDE + 1024)             // 99328

#define EDGE_ELEMS (8*NST_EDGE*128*32)   // 1179648
#define PRE_ELEMS  (2*2*128*32)          // 16384

// hi edge-local PAIR-plane index touched by edge-local super-tile tl
#define HIP(tl) ((32*(tl) + 31) / 18)

// idesc kind::f16 (fp16): dtype=F32(bit4), atype=F16=0, btype=F16=0, N=256, M=128
#define IDESC_F16_N256 ((1u<<4)|(32u<<17)|(8u<<24))

#if defined(__CUDA_ARCH_FEAT_SM103_ALL) || defined(__CUDA_ARCH_FEAT_SM100_ALL) || \
    (defined(__CUDA_ARCH_SPECIFIC__) && (__CUDA_ARCH_SPECIFIC__ >= 1000))
#define HAS_TC05 1
#else
#define HAS_TC05 0
#endif

__device__ float g_s0[BATCH*C*HW];
__device__ float g_s1[BATCH*C*HW];
__device__ __align__(16) uint32_t gA[8*NST_EDGE*128*32];  // fp16 pairs, swizzled A super-tiles
__device__ __align__(16) uint32_t gApre[PRE_ELEMS];       // pre-conv A tiles
__device__ __align__(8) unsigned short g_kdec16[2*KPAIR]; // per-edge pair: slot*PLANE + spatial
__device__ float g_asoft[8*5];

// ---------------------------------------------------------------------------
__device__ __forceinline__ uint32_t smem_u32(const void* p) {
    uint32_t a;
    asm("{ .reg .u64 t; cvta.to.shared.u64 t, %1; cvt.u32.u64 %0, t; }" : "=r"(a) : "l"(p));
    return a;
}
#define SW128(o) ((o) ^ (((o) >> 3) & 0x70))
__device__ __forceinline__ uint32_t f16x2(float lo, float hi) {
    uint32_t u;
    asm("cvt.rn.f16x2.f32 %0, %1, %2;" : "=r"(u) : "f"(hi), "f"(lo));
    return u;
}

#if HAS_TC05
__device__ __forceinline__ uint32_t elect_one() {
    uint32_t p;
    asm volatile("{ .reg .pred p; elect.sync _|p, 0xFFFFFFFF; selp.b32 %0, 1, 0, p; }" : "=r"(p));
    return p;
}
__device__ __forceinline__ uint64_t make_desc(uint32_t addr) {
    const uint64_t base = (uint64_t(2) << 61) | (uint64_t(1) << 46)
                        | (uint64_t(64) << 32) | (uint64_t(1) << 16);
    return base | ((uint64_t)(addr >> 4) & 0x3FFF);
}
__device__ __forceinline__ void mma_f16_ss(uint32_t d, uint64_t ad, uint64_t bd,
                                           uint32_t idesc, uint32_t en) {
    asm volatile(
        "{\n\t.reg .pred p;\n\tsetp.ne.u32 p, %5, 0;\n\t"
        "tcgen05.mma.cta_group::1.kind::f16 [%0], %1, %2, %3, {%4, %4, %4, %4}, p;\n\t}"
        :: "r"(d), "l"(ad), "l"(bd), "r"(idesc), "r"(0u), "r"(en) : "memory");
}
__device__ __forceinline__ void mbar_init(uint32_t a, uint32_t cnt) {
    asm volatile("mbarrier.init.shared.b64 [%0], %1;" :: "r"(a), "r"(cnt) : "memory");
}
__device__ __forceinline__ void mbar_inval(uint32_t a) {
    asm volatile("mbarrier.inval.shared.b64 [%0];" :: "r"(a) : "memory");
}
__device__ __forceinline__ void mbar_wait(uint32_t a, uint32_t parity) {
    asm volatile(
        "{\n\t.reg .pred P;\n"
        "W_%=:\n\t"
        "mbarrier.try_wait.parity.acquire.cta.shared::cta.b64 P, [%0], %1, 0x989680;\n\t"
        "@P bra D_%=;\n\tbra W_%=;\nD_%=:\n\t}"
        :: "r"(a), "r"(parity) : "memory");
}
__device__ __forceinline__ void mbar_expect_tx(uint32_t a, uint32_t bytes) {
    asm volatile("mbarrier.arrive.expect_tx.shared.b64 _, [%0], %1;"
                 :: "r"(a), "r"(bytes) : "memory");
}
__device__ __forceinline__ void bulk_g2s(uint32_t dst, const void* src,
                                         uint32_t bytes, uint32_t mbar) {
    asm volatile(
        "cp.async.bulk.shared::cta.global.mbarrier::complete_tx::bytes [%0], [%1], %2, [%3];"
        :: "r"(dst), "l"(src), "r"(bytes), "r"(mbar) : "memory");
}
__device__ __forceinline__ void tmem_commit(uint32_t mbar) {
    asm volatile(
        "tcgen05.commit.cta_group::1.mbarrier::arrive::one.shared::cluster.b64 [%0];"
        :: "r"(mbar) : "memory");
}
#define TC_ALLOC(dst, n)   asm volatile("tcgen05.alloc.cta_group::1.sync.aligned.shared::cta.b32 [%0], %1;" :: "r"(dst), "r"(n) : "memory")
#define TC_DEALLOC(t, n)   asm volatile("tcgen05.dealloc.cta_group::1.sync.aligned.b32 %0, %1;" :: "r"(t), "r"(n))
#define TC_RELINQ()        asm volatile("tcgen05.relinquish_alloc_permit.cta_group::1.sync.aligned;")
#define TC_FENCE_AFTER()   asm volatile("tcgen05.fence::after_thread_sync;" ::: "memory")
#define TC_FENCE_BEFORE()  asm volatile("tcgen05.fence::before_thread_sync;" ::: "memory")
#define TC_WAIT_LD()       asm volatile("tcgen05.wait::ld.sync.aligned;" ::: "memory")
#define FENCE_ASYNC()      asm volatile("fence.proxy.async.shared::cta;" ::: "memory")

#define LD_X32(r, a) \
    asm volatile("tcgen05.ld.sync.aligned.32x32b.x32.b32 " \
        "{%0,%1,%2,%3,%4,%5,%6,%7,%8,%9,%10,%11,%12,%13,%14,%15," \
        "%16,%17,%18,%19,%20,%21,%22,%23,%24,%25,%26,%27,%28,%29,%30,%31}, [%32];" \
        : "=r"((r)[0]),"=r"((r)[1]),"=r"((r)[2]),"=r"((r)[3]), \
          "=r"((r)[4]),"=r"((r)[5]),"=r"((r)[6]),"=r"((r)[7]), \
          "=r"((r)[8]),"=r"((r)[9]),"=r"((r)[10]),"=r"((r)[11]), \
          "=r"((r)[12]),"=r"((r)[13]),"=r"((r)[14]),"=r"((r)[15]), \
          "=r"((r)[16]),"=r"((r)[17]),"=r"((r)[18]),"=r"((r)[19]), \
          "=r"((r)[20]),"=r"((r)[21]),"=r"((r)[22]),"=r"((r)[23]), \
          "=r"((r)[24]),"=r"((r)[25]),"=r"((r)[26]),"=r"((r)[27]), \
          "=r"((r)[28]),"=r"((r)[29]),"=r"((r)[30]),"=r"((r)[31]) \
        : "r"(a))
#endif  // HAS_TC05

// ---------------------------------------------------------------------------
// prep: softmax (block 0) + pair kdec table
// ---------------------------------------------------------------------------
__global__ void k_prep(const float* __restrict__ alphas) {
    if (blockIdx.x == 0 && threadIdx.x < 8) {
        int e = threadIdx.x;
        float m = -1e30f;
        #pragma unroll
        for (int i = 0; i < 5; i++) m = fmaxf(m, alphas[e*5+i]);
        float ex[5]; float s = 0.f;
        #pragma unroll
        for (int i = 0; i < 5; i++) { ex[i] = expf(alphas[e*5+i] - m); s += ex[i]; }
        float inv = 1.f / s;
        #pragma unroll
        for (int i = 0; i < 5; i++) g_asoft[e*5+i] = ex[i] * inv;
    }
    int idx = blockIdx.x * 256 + threadIdx.x;
    if (idx >= 2*KPAIR) return;
    int e  = idx / KPAIR;
    int p  = idx - e*KPAIR;
    int cp = p / 18, t = p - cp*18;
    int dy, dx;
    if (t < 9) { dy = t/3 - 1; dx = t%3 - 1; }
    else { int u = t - 9; dy = (u/3)*2 - 2; dx = (u%3)*2 - 2; }
    int slot = (e*64 + cp) % RING_SLOTS;
    g_kdec16[idx] = (unsigned short)(slot*PLANE + (dy+2)*36 + (dx+2));
}

// ---------------------------------------------------------------------------
// combine: edge A super-tiles in PAIRED K order + pre-conv A tiles
// ---------------------------------------------------------------------------
__global__ void k_combine_all(const float* __restrict__ w3, const float* __restrict__ wd3,
                              const float* __restrict__ w_pre0, const float* __restrict__ w_pre1) {
    int idx = blockIdx.x * 256 + threadIdx.x;
    if (idx < EDGE_ELEMS) {
        int kk = idx & 31;
        int r  = idx >> 5;
        int co = r & 127;
        int est = r >> 7;
        int e  = est / NST_EDGE, st = est - e*NST_EDGE;
        int p  = st*32 + kk;
        int cp = p / 18, t = p - cp*18;
        float a = (t < 9) ? g_asoft[e*5+1] : g_asoft[e*5+2];
        int tt  = (t < 9) ? t : t - 9;
        float v2[2];
        #pragma unroll
        for (int j = 0; j < 2; j++) {
            int ci = 2*cp + j;
            float val = a * ((t < 9 ? w3 : wd3)[((e*C + co)*C + ci)*9 + tt]);
            if (co == ci && t < 9) {
                val += g_asoft[e*5+3] * (1.f/9.f);
                if (t == 4) val += g_asoft[e*5+0];
            }
            v2[j] = val;
        }
        uint32_t off = SW128((uint32_t)(co*128 + kk*4));
        *(uint32_t*)((char*)gA + (size_t)est*TILE_BYTES + off) = f16x2(v2[0], v2[1]);
    } else {
        int p = idx - EDGE_ELEMS;
        if (p >= PRE_ELEMS) return;
        int kk = p & 31;
        int r  = p >> 5;
        int co = r & 127;
        int ist = r >> 7;
        const float* w = (ist >> 1) ? w_pre1 : w_pre0;
        int ci = (ist & 1)*64 + kk*2;
        uint32_t off = SW128((uint32_t)(co*128 + kk*4));
        *(uint32_t*)((char*)gApre + (size_t)ist*TILE_BYTES + off)
            = f16x2(w[co*C + ci], w[co*C + ci + 1]);
    }
}

// ---------------------------------------------------------------------------
// tensor-core 1x1 pre-conv, both inputs in one launch (grid 512).
// ---------------------------------------------------------------------------
__global__ __launch_bounds__(256) void k_pre_mma(const float* __restrict__ in0,
                                                 const float* __restrict__ in1,
                                                 float* __restrict__ outS0,
                                                 float* __restrict__ outS1)
{
#if HAS_TC05
    extern __shared__ char dsm_raw[];
    char* dsm = (char*)(((uintptr_t)dsm_raw + 1023) & ~(uintptr_t)1023);
    __shared__ __align__(16) uint64_t mbar[2];
    __shared__ __align__(16) uint64_t abar[2];
    __shared__ uint32_t tmem_ptr_s;

    const int tid = threadIdx.x;
    const int wid = tid >> 5;
    const int which = blockIdx.x >> 8;
    const int bidx  = blockIdx.x & 255;
    const int b   = bidx >> 2;
    const int pc  = bidx & 3;
    const float* in = which ? in1 : in0;
    float* outS    = which ? outS1 : outS0;

    if (wid == 0) {
        TC_ALLOC(smem_u32(&tmem_ptr_s), 256);
        TC_RELINQ();
    }
    if (tid == 0) {
        mbar_init(smem_u32(&mbar[0]), 1);
        mbar_init(smem_u32(&mbar[1]), 1);
        mbar_init(smem_u32(&abar[0]), 1);
        mbar_init(smem_u32(&abar[1]), 1);
    }
    const uint32_t mb0 = smem_u32(&mbar[0]);
    const uint32_t mb1 = smem_u32(&mbar[1]);
    const uint32_t ab0 = smem_u32(&abar[0]);
    const uint32_t ab1 = smem_u32(&abar[1]);
    const bool leader = (wid == 0) && elect_one();

    const float* inb = in + (long long)b*C*HW + pc*256;
    int aph0 = 0, aph1 = 0;
    __syncthreads();

    for (int t = 0; t < 2; t++) {
        const int buf = t;
        const uint32_t ab = buf ? ab1 : ab0;
        const uint32_t mb = buf ? mb1 : mb0;
        if (leader) {
            mbar_expect_tx(ab, TILE_BYTES);
            bulk_g2s(smem_u32(dsm + buf*BUF_STRIDE),
                     (const char*)gApre + (size_t)(which*2 + t)*TILE_BYTES,
                     TILE_BYTES, ab);
        }
        {
            char* Bd = dsm + buf*BUF_STRIDE + TILE_BYTES;
            const float* src = inb + (t*64)*HW;
            #pragma unroll
            for (int q = 0; q < 8; q++) {
                float v[8];
                #pragma unroll
                for (int j = 0; j < 8; j++)
                    v[j] = __ldg(&src[(q*8 + j)*HW + tid]);
                uint4 o;
                o.x = f16x2(v[0], v[1]); o.y = f16x2(v[2], v[3]);
                o.z = f16x2(v[4], v[5]); o.w = f16x2(v[6], v[7]);
                uint32_t off = SW128((uint32_t)(tid*128 + q*16));
                *(uint4*)(Bd + off) = o;
            }
        }
        __syncthreads();
        if (leader) {
            FENCE_ASYNC();
            if (buf) { mbar_wait(ab1, aph1); aph1 ^= 1; }
            else     { mbar_wait(ab0, aph0); aph0 ^= 1; }
            uint64_t ad = make_desc(smem_u32(dsm + buf*BUF_STRIDE));
            uint64_t bd = make_desc(smem_u32(dsm + buf*BUF_STRIDE + TILE_BYTES));
            #pragma unroll
            for (int k = 0; k < 4; k++)
                mma_f16_ss(tmem_ptr_s, ad + k*2, bd + k*2, IDESC_F16_N256,
                           (t == 0 && k == 0) ? 0u : 1u);
            tmem_commit(mb);
        }
    }
    mbar_wait(mb1, 0);
    TC_FENCE_AFTER();
    const uint32_t tmem = tmem_ptr_s;

    {
        const int lg      = wid & 3;
        const uint32_t woff = ((uint32_t)lg) << 21;
        const int co      = lg*32 + (tid & 31);
        const int colbase = (wid >> 2) * 128;
        float* op = outS + (long long)b*REG_STRIDE + co*HW + pc*256 + colbase;
        #pragma unroll
        for (int c = 0; c < 4; c++) {
            uint32_t r[32];
            LD_X32(r, tmem + colbase + c*32 + woff);
            TC_WAIT_LD();
            #pragma unroll
            for (int j = 0; j < 8; j++)
                ((float4*)(op + c*32))[j] = make_float4(
                    __uint_as_float(r[j*4+0]), __uint_as_float(r[j*4+1]),
                    __uint_as_float(r[j*4+2]), __uint_as_float(r[j*4+3]));
        }
        TC_FENCE_BEFORE();
    }
    __syncthreads();
    if (tid == 0) { mbar_inval(mb0); mbar_inval(mb1); mbar_inval(ab0); mbar_inval(ab1); }
    __syncthreads();
    if (wid == 0) TC_DEALLOC(tmem, 256);
#endif  // HAS_TC05
}

// ---------------------------------------------------------------------------
// tcgen05 fp16 node kernel (R13 core) + fused in-loop maxp REDs + next-region
// zeroing.  out region must be pre-zeroed; conv epilogue and maxp both use
// atomicAdd (order-free, deterministic since fp add is commutative).
// ---------------------------------------------------------------------------
__global__ __launch_bounds__(256) void k_node_mma(
    const float* __restrict__ h0, int h0bs,
    const float* __restrict__ h1, int h1bs,
    float* __restrict__ outR, float* __restrict__ outNext, int eA, int eB)
{
#if HAS_TC05
    extern __shared__ char dsm_raw[];
    char* dsm = (char*)(((uintptr_t)dsm_raw + 1023) & ~(uintptr_t)1023);
    uint32_t* ring = (uint32_t*)(dsm + OFF_STAGE);   // [slot(9)][PLANE] f16x2
    __shared__ __align__(16) uint64_t mbar[2];
    __shared__ __align__(16) uint64_t abar[2];
    __shared__ uint32_t tmem_ptr_s;

    const int tid = threadIdx.x;
    const int wid = tid >> 5;
    const int b   = blockIdx.x >> 2;
    const int pc  = blockIdx.x & 3;

    if (wid == 0) {
        TC_ALLOC(smem_u32(&tmem_ptr_s), 256);
        TC_RELINQ();
    }
    if (tid == 0) {
        mbar_init(smem_u32(&mbar[0]), 1);
        mbar_init(smem_u32(&mbar[1]), 1);
        mbar_init(smem_u32(&abar[0]), 1);
        mbar_init(smem_u32(&abar[1]), 1);
    }
    const uint32_t mb0 = smem_u32(&mbar[0]);
    const uint32_t mb1 = smem_u32(&mbar[1]);
    const uint32_t ab0 = smem_u32(&abar[0]);
    const uint32_t ab1 = smem_u32(&abar[1]);
    const bool leader = (wid == 0) && elect_one();

    const int px    = tid;
    const int y0    = pc*8;
    const int tbase = (px >> 5)*36 + (px & 31);
    const float* hA = h0 + (long long)b * h0bs;
    const float* hB = h1 + (long long)b * h1bs;

    int go0, go1; bool va0, va1; const bool has1 = (tid + 256) < PLANE;
    {
        int p = tid, row = p/36, col = p - (p/36)*36;
        int gy = y0 + row - 2, gx = col - 2;
        va0 = ((unsigned)gy < 32u) && ((unsigned)gx < 32u);
        go0 = gy*32 + gx;
        p = tid + 256; row = p/36; col = p - row*36;
        gy = y0 + row - 2; gx = col - 2;
        va1 = ((unsigned)gy < 32u) && ((unsigned)gx < 32u);
        go1 = gy*32 + gx;
    }
    float pv[2][2][2];              // [pair j][pixel][channel lo/hi]
    int   npl_lo = 0, npl_cnt = 0;  // edge-local pair-plane range
    int   npl_glob = 0;
    const float* npl_img = hA;

    auto calc_planes = [&](int tt) {
        int e = tt / NST_EDGE, tl = tt - e*NST_EDGE;
        npl_img = e ? hB : hA;
        int lo, hi = HIP(tl);
        if (tl == 0) lo = 0; else lo = HIP(tl - 1) + 1;
        npl_lo = lo; npl_cnt = hi - lo + 1;
        npl_glob = e*64 + lo;
    };
    auto stage_load = [&]() {
        #pragma unroll
        for (int j = 0; j < 2; j++) {
            if (j < npl_cnt) {
                const float* pl = npl_img + (size_t)(2*(npl_lo + j))*HW;
                pv[j][0][0] = va0 ? __ldg(&pl[go0]) : 0.f;
                pv[j][0][1] = va0 ? __ldg(&pl[HW + go0]) : 0.f;
                pv[j][1][0] = (has1 && va1) ? __ldg(&pl[go1]) : 0.f;
                pv[j][1][1] = (has1 && va1) ? __ldg(&pl[HW + go1]) : 0.f;
            }
        }
    };
    auto stage_store = [&]() {
        #pragma unroll
        for (int j = 0; j < 2; j++) {
            if (j < npl_cnt) {
                uint32_t* sl = ring + ((npl_glob + j) % RING_SLOTS)*PLANE;
                sl[tid] = f16x2(pv[j][0][0], pv[j][0][1]);
                if (has1) sl[tid + 256] = f16x2(pv[j][1][0], pv[j][1][1]);
            }
        }
    };

    // ---- fused maxp setup: thread -> (row y0+my, col mx) ----
    const float a4A = g_asoft[eA*5+4];
    const float a4B = g_asoft[eB*5+4];
    const int my  = tid >> 5;            // 0..7
    const int mx  = tid & 31;
    const int gyc = y0 + my;
    float* outPx = outR + (long long)b*OUT_BSTRIDE + gyc*32 + mx;  // + co*HW
    float* znBase = outNext ? (outNext + (long long)b*OUT_BSTRIDE + pc*256) : nullptr;

    int ph0 = 0, ph1 = 0;
    int aph0 = 0, aph1 = 0;

    calc_planes(0);
    stage_load();
    stage_store();
    __syncthreads();

    for (int t = 0; t < NTILES; t++) {
        const int buf = t & 1;
        const uint32_t mb = buf ? mb1 : mb0;
        const uint32_t ab = buf ? ab1 : ab0;
        if (t >= 2) {
            if (buf) { mbar_wait(mb1, ph1); ph1 ^= 1; }
            else     { mbar_wait(mb0, ph0); ph0 ^= 1; }
        }
        const int e  = (t < NST_EDGE) ? 0 : 1;
        const int te = t - e*NST_EDGE;
        const int eg = e ? eB : eA;
        if (leader) {
            mbar_expect_tx(ab, TILE_BYTES);
            bulk_g2s(smem_u32(dsm + buf*BUF_STRIDE),
                     (const char*)gA + (size_t)(eg*NST_EDGE + te)*TILE_BYTES,
                     TILE_BYTES, ab);
        }
        if (t + 1 < NTILES) { calc_planes(t + 1); stage_load(); }
        else npl_cnt = 0;
        // ---- B build: 32 pair gathers (LDS.32, f16x2) -> 8 STS.128 ----
        {
            char* Bd = dsm + buf*BUF_STRIDE + TILE_BYTES;
            const ushort4* kdp = (const ushort4*)(g_kdec16 + e*KPAIR + te*32);
            #pragma unroll
            for (int q = 0; q < 8; q++) {
                ushort4 k4 = __ldg(&kdp[q]);
                uint4 o;
                o.x = ring[k4.x + tbase];
                o.y = ring[k4.y + tbase];
                o.z = ring[k4.z + tbase];
                o.w = ring[k4.w + tbase];
                uint32_t off = SW128((uint32_t)(px*128 + q*16));
                *(uint4*)(Bd + off) = o;
            }
        }
        stage_store();
        // ---- fused maxp: 2 channels per tile (tiles 0..63 cover 128 co) ----
        if (t < 64) {
            #pragma unroll
            for (int cc = 0; cc < 2; cc++) {
                int co = 2*t + cc;
                float acc = 0.f;
                #pragma unroll
                for (int e2 = 0; e2 < 2; e2++) {
                    const float* img = (e2 ? hB : hA) + (size_t)co*HW;
                    float m = -INFINITY;
                    #pragma unroll
                    for (int dy = -1; dy <= 1; dy++) {
                        int gy = gyc + dy;
                        if ((unsigned)gy < 32u) {
                            float v = __ldg(&img[gy*32 + mx]);
                            float l = __shfl_up_sync(0xffffffffu, v, 1);
                            float r = __shfl_down_sync(0xffffffffu, v, 1);
                            if (mx == 0)  l = -INFINITY;
                            if (mx == 31) r = -INFINITY;
                            m = fmaxf(m, fmaxf(v, fmaxf(l, r)));
                        }
                    }
                    acc += (e2 ? a4B : a4A) * m;
                }
                atomicAdd(outPx + (size_t)co*HW, acc);
            }
        }
        // ---- zero next node's region slice (tiles 0..31, 1 float4/thread) ----
        if (znBase && t < 32) {
            int i4  = t*256 + tid;          // float4 index in 128co x 64f4
            int co  = i4 >> 6;
            int rem = i4 & 63;
            *(float4*)(znBase + (size_t)co*HW + rem*4) = make_float4(0.f, 0.f, 0.f, 0.f);
        }
        __syncthreads();
        if (leader) {
            FENCE_ASYNC();
            if (buf) { mbar_wait(ab1, aph1); aph1 ^= 1; }
            else     { mbar_wait(ab0, aph0); aph0 ^= 1; }
            uint64_t ad = make_desc(smem_u32(dsm + buf*BUF_STRIDE));
            uint64_t bd = make_desc(smem_u32(dsm + buf*BUF_STRIDE + TILE_BYTES));
            #pragma unroll
            for (int k = 0; k < 4; k++)
                mma_f16_ss(tmem_ptr_s, ad + k*2, bd + k*2, IDESC_F16_N256,
                           (t == 0 && k == 0) ? 0u : 1u);
            tmem_commit(mb);
        }
    }
    mbar_wait(mb1, ph1);
    TC_FENCE_AFTER();
    const uint32_t tmem = tmem_ptr_s;

    // ---- epilogue: conv result added via REDs (region pre-zeroed) ----
    {
        const int lg      = wid & 3;
        const uint32_t woff = ((uint32_t)lg) << 21;
        const int co      = lg*32 + (tid & 31);
        const int colbase = (wid >> 2) * 128;
        float* op = outR + (long long)b*OUT_BSTRIDE + co*HW + pc*256 + colbase;
        #pragma unroll
        for (int c = 0; c < 4; c++) {
            uint32_t r[32];
            LD_X32(r, tmem + colbase + c*32 + woff);
            TC_WAIT_LD();
            #pragma unroll
            for (int j = 0; j < 8; j++) {
                float* q = op + c*32 + j*4;
                atomicAdd(q + 0, __uint_as_float(r[j*4+0]));
                atomicAdd(q + 1, __uint_as_float(r[j*4+1]));
                atomicAdd(q + 2, __uint_as_float(r[j*4+2]));
                atomicAdd(q + 3, __uint_as_float(r[j*4+3]));
            }
        }
        TC_FENCE_BEFORE();
    }
    __syncthreads();
    if (tid == 0) { mbar_inval(mb0); mbar_inval(mb1); mbar_inval(ab0); mbar_inval(ab1); }
    __syncthreads();
    if (wid == 0) TC_DEALLOC(tmem, 256);
#endif  // HAS_TC05
}

// ---------------------------------------------------------------------------
// copy skip into concat + second output; ALSO zero region 0 (node 0 adds).
// ---------------------------------------------------------------------------
__global__ void k_copy_skip(const float* __restrict__ skip,
                            float* __restrict__ out,
                            float* __restrict__ out2) {
    int i = blockIdx.x * 256 + threadIdx.x;
    if (i >= (BATCH*C*HW)/4) return;
    float4 v = ((const float4*)skip)[i];
    int pe = i * 4;
    int b  = pe >> 17;
    int r  = pe & (C*HW - 1);
    *(float4*)(out + (long long)b*OUT_BSTRIDE + 4*C*HW + r) = v;
    *(float4*)(out + (long long)b*OUT_BSTRIDE + r) = make_float4(0.f, 0.f, 0.f, 0.f);
    if (out2) ((float4*)out2)[i] = v;
}

// ---------------------------------------------------------------------------
extern "C" void kernel_launch(void* const* d_in, const int* in_sizes, int n_in,
                              void* d_out, int out_size) {
    const float* input0 = (const float*)d_in[0];
    const float* input1 = (const float*)d_in[1];
    const float* skip   = (const float*)d_in[2];
    const float* w_pre0 = (const float*)d_in[3];
    const float* w_pre1 = (const float*)d_in[4];
    const float* w3     = (const float*)d_in[5];
    const float* wd3    = (const float*)d_in[6];
    const float* alphas = (const float*)d_in[7];
    float* out = (float*)d_out;

    float *s0, *s1;
    cudaGetSymbolAddress((void**)&s0, g_s0);
    cudaGetSymbolAddress((void**)&s1, g_s1);

    cudaFuncSetAttribute(k_node_mma, cudaFuncAttributeMaxDynamicSharedMemorySize, DSMEM_SZ);
    cudaFuncSetAttribute(k_pre_mma,  cudaFuncAttributeMaxDynamicSharedMemorySize, DSMEM_PRE);

    long long concat_elems = (long long)BATCH*OUTC*HW;
    long long skip_elems   = (long long)BATCH*C*HW;
    float* out2 = nullptr;
    if ((long long)out_size >= concat_elems + skip_elems)
        out2 = out + concat_elems;

    k_prep<<<(2*KPAIR + 255)/256, 256>>>(alphas);
    k_combine_all<<<(EDGE_ELEMS + PRE_ELEMS + 255)/256, 256>>>(w3, wd3, w_pre0, w_pre1);
    k_pre_mma<<<2*BATCH*4, 256, DSMEM_PRE>>>(input0, input1, s0, s1);
    k_copy_skip<<<((BATCH*C*HW/4) + 255)/256, 256>>>(skip, out, out2);   // zeroes region 0

    float* r0 = out + 0*C*HW;
    float* r1 = out + 1*C*HW;
    float* r2 = out + 2*C*HW;
    float* r3 = out + 3*C*HW;

    k_node_mma<<<BATCH*4, 256, DSMEM_SZ>>>(s0, REG_STRIDE, s1, REG_STRIDE, r0, r1, 0, 1);
    k_node_mma<<<BATCH*4, 256, DSMEM_SZ>>>(s1, REG_STRIDE, r0, OUT_BSTRIDE, r1, r2, 2, 3);
    k_node_mma<<<BATCH*4, 256, DSMEM_SZ>>>(r0, OUT_BSTRIDE, r1, OUT_BSTRIDE, r2, r3, 4, 5);
    k_node_mma<<<BATCH*4, 256, DSMEM_SZ>>>(r1, OUT_BSTRIDE, r2, OUT_BSTRIDE, r3, nullptr, 6, 7);
}

// round 16
// speedup vs baseline: 1.9015x; 1.9015x over previous
#include <cuda_runtime.h>
#include <math.h>
#include <stdint.h>

#define BATCH 64
#define C 128
#define HW 1024
#define OUTC 640
#define REG_STRIDE (C*HW)
#define OUT_BSTRIDE (OUTC*HW)

#define KPAIR 1152            // per edge: 64 ci-pairs * 18 taps
#define NST_EDGE 36           // super-tiles (32 pairs = 64 k) per edge
#define NTILES 72             // 2 edges
#define TILE_BYTES 16384      // A super-tile: 128 co x 64 k fp16 = 128B rows
#define BTILE_BYTES 32768     // B super-tile: 256 px x 64 k fp16 = 128B rows
#define BUF_STRIDE (TILE_BYTES + BTILE_BYTES)   // 49152
#define PLANE 432             // pair-plane: 12 rows * 36 cols (f16x2 per px)
#define RING_SLOTS 9
#define RING_BYTES (RING_SLOTS*PLANE*4)         // 15552
#define OFF_STAGE (2*BUF_STRIDE)                // 98304
#define DSMEM_SZ  (OFF_STAGE + RING_BYTES + 1024)   // 114880
#define DSMEM_PRE (2*BUF_STRIDE + 1024)             // 99328

#define EDGE_ELEMS (8*NST_EDGE*128*32)   // 1179648
#define PRE_ELEMS  (2*2*128*32)          // 16384

// hi edge-local PAIR-plane index touched by edge-local super-tile tl
#define HIP(tl) ((32*(tl) + 31) / 18)

// idesc kind::f16 (fp16): dtype=F32(bit4), atype=F16=0, btype=F16=0, N=256, M=128
#define IDESC_F16_N256 ((1u<<4)|(32u<<17)|(8u<<24))

#if defined(__CUDA_ARCH_FEAT_SM103_ALL) || defined(__CUDA_ARCH_FEAT_SM100_ALL) || \
    (defined(__CUDA_ARCH_SPECIFIC__) && (__CUDA_ARCH_SPECIFIC__ >= 1000))
#define HAS_TC05 1
#else
#define HAS_TC05 0
#endif

__device__ float g_s0[BATCH*C*HW];
__device__ float g_s1[BATCH*C*HW];
__device__ __align__(16) uint32_t gA[8*NST_EDGE*128*32];  // fp16 pairs, swizzled A super-tiles
__device__ __align__(16) uint32_t gApre[PRE_ELEMS];       // pre-conv A tiles
__device__ __align__(8) unsigned short g_kdec16[2*KPAIR]; // per-edge pair: slot*PLANE + spatial
__device__ float g_asoft[8*5];

// ---------------------------------------------------------------------------
__device__ __forceinline__ uint32_t smem_u32(const void* p) {
    uint32_t a;
    asm("{ .reg .u64 t; cvta.to.shared.u64 t, %1; cvt.u32.u64 %0, t; }" : "=r"(a) : "l"(p));
    return a;
}
#define SW128(o) ((o) ^ (((o) >> 3) & 0x70))
__device__ __forceinline__ uint32_t f16x2(float lo, float hi) {
    uint32_t u;
    asm("cvt.rn.f16x2.f32 %0, %1, %2;" : "=r"(u) : "f"(hi), "f"(lo));
    return u;
}

#if HAS_TC05
__device__ __forceinline__ uint32_t elect_one() {
    uint32_t p;
    asm volatile("{ .reg .pred p; elect.sync _|p, 0xFFFFFFFF; selp.b32 %0, 1, 0, p; }" : "=r"(p));
    return p;
}
__device__ __forceinline__ uint64_t make_desc(uint32_t addr) {
    const uint64_t base = (uint64_t(2) << 61) | (uint64_t(1) << 46)
                        | (uint64_t(64) << 32) | (uint64_t(1) << 16);
    return base | ((uint64_t)(addr >> 4) & 0x3FFF);
}
__device__ __forceinline__ void mma_f16_ss(uint32_t d, uint64_t ad, uint64_t bd,
                                           uint32_t idesc, uint32_t en) {
    asm volatile(
        "{\n\t.reg .pred p;\n\tsetp.ne.u32 p, %5, 0;\n\t"
        "tcgen05.mma.cta_group::1.kind::f16 [%0], %1, %2, %3, {%4, %4, %4, %4}, p;\n\t}"
        :: "r"(d), "l"(ad), "l"(bd), "r"(idesc), "r"(0u), "r"(en) : "memory");
}
__device__ __forceinline__ void mbar_init(uint32_t a, uint32_t cnt) {
    asm volatile("mbarrier.init.shared.b64 [%0], %1;" :: "r"(a), "r"(cnt) : "memory");
}
__device__ __forceinline__ void mbar_inval(uint32_t a) {
    asm volatile("mbarrier.inval.shared.b64 [%0];" :: "r"(a) : "memory");
}
__device__ __forceinline__ void mbar_wait(uint32_t a, uint32_t parity) {
    asm volatile(
        "{\n\t.reg .pred P;\n"
        "W_%=:\n\t"
        "mbarrier.try_wait.parity.acquire.cta.shared::cta.b64 P, [%0], %1, 0x989680;\n\t"
        "@P bra D_%=;\n\tbra W_%=;\nD_%=:\n\t}"
        :: "r"(a), "r"(parity) : "memory");
}
__device__ __forceinline__ void mbar_expect_tx(uint32_t a, uint32_t bytes) {
    asm volatile("mbarrier.arrive.expect_tx.shared.b64 _, [%0], %1;"
                 :: "r"(a), "r"(bytes) : "memory");
}
__device__ __forceinline__ void bulk_g2s(uint32_t dst, const void* src,
                                         uint32_t bytes, uint32_t mbar) {
    asm volatile(
        "cp.async.bulk.shared::cta.global.mbarrier::complete_tx::bytes [%0], [%1], %2, [%3];"
        :: "r"(dst), "l"(src), "r"(bytes), "r"(mbar) : "memory");
}
__device__ __forceinline__ void tmem_commit(uint32_t mbar) {
    asm volatile(
        "tcgen05.commit.cta_group::1.mbarrier::arrive::one.shared::cluster.b64 [%0];"
        :: "r"(mbar) : "memory");
}
#define TC_ALLOC(dst, n)   asm volatile("tcgen05.alloc.cta_group::1.sync.aligned.shared::cta.b32 [%0], %1;" :: "r"(dst), "r"(n) : "memory")
#define TC_DEALLOC(t, n)   asm volatile("tcgen05.dealloc.cta_group::1.sync.aligned.b32 %0, %1;" :: "r"(t), "r"(n))
#define TC_RELINQ()        asm volatile("tcgen05.relinquish_alloc_permit.cta_group::1.sync.aligned;")
#define TC_FENCE_AFTER()   asm volatile("tcgen05.fence::after_thread_sync;" ::: "memory")
#define TC_FENCE_BEFORE()  asm volatile("tcgen05.fence::before_thread_sync;" ::: "memory")
#define TC_WAIT_LD()       asm volatile("tcgen05.wait::ld.sync.aligned;" ::: "memory")
#define FENCE_ASYNC()      asm volatile("fence.proxy.async.shared::cta;" ::: "memory")

#define LD_X32(r, a) \
    asm volatile("tcgen05.ld.sync.aligned.32x32b.x32.b32 " \
        "{%0,%1,%2,%3,%4,%5,%6,%7,%8,%9,%10,%11,%12,%13,%14,%15," \
        "%16,%17,%18,%19,%20,%21,%22,%23,%24,%25,%26,%27,%28,%29,%30,%31}, [%32];" \
        : "=r"((r)[0]),"=r"((r)[1]),"=r"((r)[2]),"=r"((r)[3]), \
          "=r"((r)[4]),"=r"((r)[5]),"=r"((r)[6]),"=r"((r)[7]), \
          "=r"((r)[8]),"=r"((r)[9]),"=r"((r)[10]),"=r"((r)[11]), \
          "=r"((r)[12]),"=r"((r)[13]),"=r"((r)[14]),"=r"((r)[15]), \
          "=r"((r)[16]),"=r"((r)[17]),"=r"((r)[18]),"=r"((r)[19]), \
          "=r"((r)[20]),"=r"((r)[21]),"=r"((r)[22]),"=r"((r)[23]), \
          "=r"((r)[24]),"=r"((r)[25]),"=r"((r)[26]),"=r"((r)[27]), \
          "=r"((r)[28]),"=r"((r)[29]),"=r"((r)[30]),"=r"((r)[31]) \
        : "r"(a))
#endif  // HAS_TC05

// ---------------------------------------------------------------------------
// prep: softmax (block 0) + pair kdec table
// ---------------------------------------------------------------------------
__global__ void k_prep(const float* __restrict__ alphas) {
    if (blockIdx.x == 0 && threadIdx.x < 8) {
        int e = threadIdx.x;
        float m = -1e30f;
        #pragma unroll
        for (int i = 0; i < 5; i++) m = fmaxf(m, alphas[e*5+i]);
        float ex[5]; float s = 0.f;
        #pragma unroll
        for (int i = 0; i < 5; i++) { ex[i] = expf(alphas[e*5+i] - m); s += ex[i]; }
        float inv = 1.f / s;
        #pragma unroll
        for (int i = 0; i < 5; i++) g_asoft[e*5+i] = ex[i] * inv;
    }
    int idx = blockIdx.x * 256 + threadIdx.x;
    if (idx >= 2*KPAIR) return;
    int e  = idx / KPAIR;
    int p  = idx - e*KPAIR;
    int cp = p / 18, t = p - cp*18;
    int dy, dx;
    if (t < 9) { dy = t/3 - 1; dx = t%3 - 1; }
    else { int u = t - 9; dy = (u/3)*2 - 2; dx = (u%3)*2 - 2; }
    int slot = (e*64 + cp) % RING_SLOTS;
    g_kdec16[idx] = (unsigned short)(slot*PLANE + (dy+2)*36 + (dx+2));
}

// ---------------------------------------------------------------------------
// combine: edge A super-tiles in PAIRED K order + pre-conv A tiles
// ---------------------------------------------------------------------------
__global__ void k_combine_all(const float* __restrict__ w3, const float* __restrict__ wd3,
                              const float* __restrict__ w_pre0, const float* __restrict__ w_pre1) {
    int idx = blockIdx.x * 256 + threadIdx.x;
    if (idx < EDGE_ELEMS) {
        int kk = idx & 31;
        int r  = idx >> 5;
        int co = r & 127;
        int est = r >> 7;
        int e  = est / NST_EDGE, st = est - e*NST_EDGE;
        int p  = st*32 + kk;
        int cp = p / 18, t = p - cp*18;
        float a = (t < 9) ? g_asoft[e*5+1] : g_asoft[e*5+2];
        int tt  = (t < 9) ? t : t - 9;
        float v2[2];
        #pragma unroll
        for (int j = 0; j < 2; j++) {
            int ci = 2*cp + j;
            float val = a * ((t < 9 ? w3 : wd3)[((e*C + co)*C + ci)*9 + tt]);
            if (co == ci && t < 9) {
                val += g_asoft[e*5+3] * (1.f/9.f);
                if (t == 4) val += g_asoft[e*5+0];
            }
            v2[j] = val;
        }
        uint32_t off = SW128((uint32_t)(co*128 + kk*4));
        *(uint32_t*)((char*)gA + (size_t)est*TILE_BYTES + off) = f16x2(v2[0], v2[1]);
    } else {
        int p = idx - EDGE_ELEMS;
        if (p >= PRE_ELEMS) return;
        int kk = p & 31;
        int r  = p >> 5;
        int co = r & 127;
        int ist = r >> 7;
        const float* w = (ist >> 1) ? w_pre1 : w_pre0;
        int ci = (ist & 1)*64 + kk*2;
        uint32_t off = SW128((uint32_t)(co*128 + kk*4));
        *(uint32_t*)((char*)gApre + (size_t)ist*TILE_BYTES + off)
            = f16x2(w[co*C + ci], w[co*C + ci + 1]);
    }
}

// ---------------------------------------------------------------------------
// tensor-core 1x1 pre-conv, both inputs in one launch (grid 512).
// ---------------------------------------------------------------------------
__global__ __launch_bounds__(256) void k_pre_mma(const float* __restrict__ in0,
                                                 const float* __restrict__ in1,
                                                 float* __restrict__ outS0,
                                                 float* __restrict__ outS1)
{
#if HAS_TC05
    extern __shared__ char dsm_raw[];
    char* dsm = (char*)(((uintptr_t)dsm_raw + 1023) & ~(uintptr_t)1023);
    __shared__ __align__(16) uint64_t mbar[2];
    __shared__ __align__(16) uint64_t abar[2];
    __shared__ uint32_t tmem_ptr_s;

    const int tid = threadIdx.x;
    const int wid = tid >> 5;
    const int which = blockIdx.x >> 8;
    const int bidx  = blockIdx.x & 255;
    const int b   = bidx >> 2;
    const int pc  = bidx & 3;
    const float* in = which ? in1 : in0;
    float* outS    = which ? outS1 : outS0;

    if (wid == 0) {
        TC_ALLOC(smem_u32(&tmem_ptr_s), 256);
        TC_RELINQ();
    }
    if (tid == 0) {
        mbar_init(smem_u32(&mbar[0]), 1);
        mbar_init(smem_u32(&mbar[1]), 1);
        mbar_init(smem_u32(&abar[0]), 1);
        mbar_init(smem_u32(&abar[1]), 1);
    }
    const uint32_t mb0 = smem_u32(&mbar[0]);
    const uint32_t mb1 = smem_u32(&mbar[1]);
    const uint32_t ab0 = smem_u32(&abar[0]);
    const uint32_t ab1 = smem_u32(&abar[1]);
    const bool leader = (wid == 0) && elect_one();

    const float* inb = in + (long long)b*C*HW + pc*256;
    int aph0 = 0, aph1 = 0;
    __syncthreads();

    for (int t = 0; t < 2; t++) {
        const int buf = t;
        const uint32_t ab = buf ? ab1 : ab0;
        const uint32_t mb = buf ? mb1 : mb0;
        if (leader) {
            mbar_expect_tx(ab, TILE_BYTES);
            bulk_g2s(smem_u32(dsm + buf*BUF_STRIDE),
                     (const char*)gApre + (size_t)(which*2 + t)*TILE_BYTES,
                     TILE_BYTES, ab);
        }
        {
            char* Bd = dsm + buf*BUF_STRIDE + TILE_BYTES;
            const float* src = inb + (t*64)*HW;
            #pragma unroll
            for (int q = 0; q < 8; q++) {
                float v[8];
                #pragma unroll
                for (int j = 0; j < 8; j++)
                    v[j] = __ldg(&src[(q*8 + j)*HW + tid]);
                uint4 o;
                o.x = f16x2(v[0], v[1]); o.y = f16x2(v[2], v[3]);
                o.z = f16x2(v[4], v[5]); o.w = f16x2(v[6], v[7]);
                uint32_t off = SW128((uint32_t)(tid*128 + q*16));
                *(uint4*)(Bd + off) = o;
            }
        }
        __syncthreads();
        if (leader) {
            FENCE_ASYNC();
            if (buf) { mbar_wait(ab1, aph1); aph1 ^= 1; }
            else     { mbar_wait(ab0, aph0); aph0 ^= 1; }
            uint64_t ad = make_desc(smem_u32(dsm + buf*BUF_STRIDE));
            uint64_t bd = make_desc(smem_u32(dsm + buf*BUF_STRIDE + TILE_BYTES));
            #pragma unroll
            for (int k = 0; k < 4; k++)
                mma_f16_ss(tmem_ptr_s, ad + k*2, bd + k*2, IDESC_F16_N256,
                           (t == 0 && k == 0) ? 0u : 1u);
            tmem_commit(mb);
        }
    }
    mbar_wait(mb1, 0);
    TC_FENCE_AFTER();
    const uint32_t tmem = tmem_ptr_s;

    {
        const int lg      = wid & 3;
        const uint32_t woff = ((uint32_t)lg) << 21;
        const int co      = lg*32 + (tid & 31);
        const int colbase = (wid >> 2) * 128;
        float* op = outS + (long long)b*REG_STRIDE + co*HW + pc*256 + colbase;
        #pragma unroll
        for (int c = 0; c < 4; c++) {
            uint32_t r[32];
            LD_X32(r, tmem + colbase + c*32 + woff);
            TC_WAIT_LD();
            #pragma unroll
            for (int j = 0; j < 8; j++)
                ((float4*)(op + c*32))[j] = make_float4(
                    __uint_as_float(r[j*4+0]), __uint_as_float(r[j*4+1]),
                    __uint_as_float(r[j*4+2]), __uint_as_float(r[j*4+3]));
        }
        TC_FENCE_BEFORE();
    }
    __syncthreads();
    if (tid == 0) { mbar_inval(mb0); mbar_inval(mb1); mbar_inval(ab0); mbar_inval(ab1); }
    __syncthreads();
    if (wid == 0) TC_DEALLOC(tmem, 256);
#endif  // HAS_TC05
}

// ---------------------------------------------------------------------------
// tcgen05 fp16 node kernel: R13 core + hoisted STS offsets + batched kdec.
// ---------------------------------------------------------------------------
__global__ __launch_bounds__(256) void k_node_mma(
    const float* __restrict__ h0, int h0bs,
    const float* __restrict__ h1, int h1bs,
    float* __restrict__ outR, int eA, int eB)
{
#if HAS_TC05
    extern __shared__ char dsm_raw[];
    char* dsm = (char*)(((uintptr_t)dsm_raw + 1023) & ~(uintptr_t)1023);
    uint32_t* ring = (uint32_t*)(dsm + OFF_STAGE);   // [slot(9)][PLANE] f16x2
    __shared__ __align__(16) uint64_t mbar[2];
    __shared__ __align__(16) uint64_t abar[2];
    __shared__ uint32_t tmem_ptr_s;

    const int tid = threadIdx.x;
    const int wid = tid >> 5;
    const int b   = blockIdx.x >> 2;
    const int pc  = blockIdx.x & 3;

    if (wid == 0) {
        TC_ALLOC(smem_u32(&tmem_ptr_s), 256);
        TC_RELINQ();
    }
    if (tid == 0) {
        mbar_init(smem_u32(&mbar[0]), 1);
        mbar_init(smem_u32(&mbar[1]), 1);
        mbar_init(smem_u32(&abar[0]), 1);
        mbar_init(smem_u32(&abar[1]), 1);
    }
    const uint32_t mb0 = smem_u32(&mbar[0]);
    const uint32_t mb1 = smem_u32(&mbar[1]);
    const uint32_t ab0 = smem_u32(&abar[0]);
    const uint32_t ab1 = smem_u32(&abar[1]);
    const bool leader = (wid == 0) && elect_one();

    const int px    = tid;
    const int y0    = pc*8;
    const int tbase = (px >> 5)*36 + (px & 31);
    const float* hA = h0 + (long long)b * h0bs;
    const float* hB = h1 + (long long)b * h1bs;

    // hoisted swizzled STS offsets (thread-invariant)
    uint32_t soff[8];
    #pragma unroll
    for (int q = 0; q < 8; q++) soff[q] = SW128((uint32_t)(px*128 + q*16));

    int go0, go1; bool va0, va1; const bool has1 = (tid + 256) < PLANE;
    {
        int p = tid, row = p/36, col = p - (p/36)*36;
        int gy = y0 + row - 2, gx = col - 2;
        va0 = ((unsigned)gy < 32u) && ((unsigned)gx < 32u);
        go0 = gy*32 + gx;
        p = tid + 256; row = p/36; col = p - row*36;
        gy = y0 + row - 2; gx = col - 2;
        va1 = ((unsigned)gy < 32u) && ((unsigned)gx < 32u);
        go1 = gy*32 + gx;
    }
    float pv[2][2][2];              // [pair j][pixel][channel lo/hi]
    int   npl_lo = 0, npl_cnt = 0;  // edge-local pair-plane range
    int   npl_glob = 0;
    const float* npl_img = hA;

    auto calc_planes = [&](int tt) {
        int e = tt / NST_EDGE, tl = tt - e*NST_EDGE;
        npl_img = e ? hB : hA;
        int lo, hi = HIP(tl);
        if (tl == 0) lo = 0; else lo = HIP(tl - 1) + 1;
        npl_lo = lo; npl_cnt = hi - lo + 1;
        npl_glob = e*64 + lo;
    };
    auto stage_load = [&]() {
        #pragma unroll
        for (int j = 0; j < 2; j++) {
            if (j < npl_cnt) {
                const float* pl = npl_img + (size_t)(2*(npl_lo + j))*HW;
                pv[j][0][0] = va0 ? __ldg(&pl[go0]) : 0.f;
                pv[j][0][1] = va0 ? __ldg(&pl[HW + go0]) : 0.f;
                pv[j][1][0] = (has1 && va1) ? __ldg(&pl[go1]) : 0.f;
                pv[j][1][1] = (has1 && va1) ? __ldg(&pl[HW + go1]) : 0.f;
            }
        }
    };
    auto stage_store = [&]() {
        #pragma unroll
        for (int j = 0; j < 2; j++) {
            if (j < npl_cnt) {
                uint32_t* sl = ring + ((npl_glob + j) % RING_SLOTS)*PLANE;
                sl[tid] = f16x2(pv[j][0][0], pv[j][0][1]);
                if (has1) sl[tid + 256] = f16x2(pv[j][1][0], pv[j][1][1]);
            }
        }
    };

    int ph0 = 0, ph1 = 0;
    int aph0 = 0, aph1 = 0;

    calc_planes(0);
    stage_load();
    stage_store();
    __syncthreads();

    for (int t = 0; t < NTILES; t++) {
        const int buf = t & 1;
        const uint32_t mb = buf ? mb1 : mb0;
        const uint32_t ab = buf ? ab1 : ab0;
        if (t >= 2) {
            if (buf) { mbar_wait(mb1, ph1); ph1 ^= 1; }
            else     { mbar_wait(mb0, ph0); ph0 ^= 1; }
        }
        const int e  = (t < NST_EDGE) ? 0 : 1;
        const int te = t - e*NST_EDGE;
        const int eg = e ? eB : eA;
        if (leader) {
            mbar_expect_tx(ab, TILE_BYTES);
            bulk_g2s(smem_u32(dsm + buf*BUF_STRIDE),
                     (const char*)gA + (size_t)(eg*NST_EDGE + te)*TILE_BYTES,
                     TILE_BYTES, ab);
        }
        // batched kdec loads (MLP; off the dependent build chain)
        ushort4 k4[8];
        {
            const ushort4* kdp = (const ushort4*)(g_kdec16 + e*KPAIR + te*32);
            #pragma unroll
            for (int q = 0; q < 8; q++) k4[q] = __ldg(&kdp[q]);
        }
        if (t + 1 < NTILES) { calc_planes(t + 1); stage_load(); }
        else npl_cnt = 0;
        // ---- B build: 32 pair gathers (LDS.32, f16x2) -> 8 STS.128 ----
        {
            char* Bd = dsm + buf*BUF_STRIDE + TILE_BYTES;
            #pragma unroll
            for (int q = 0; q < 8; q++) {
                uint4 o;
                o.x = ring[k4[q].x + tbase];
                o.y = ring[k4[q].y + tbase];
                o.z = ring[k4[q].z + tbase];
                o.w = ring[k4[q].w + tbase];
                *(uint4*)(Bd + soff[q]) = o;
            }
        }
        stage_store();
        __syncthreads();
        if (leader) {
            FENCE_ASYNC();
            if (buf) { mbar_wait(ab1, aph1); aph1 ^= 1; }
            else     { mbar_wait(ab0, aph0); aph0 ^= 1; }
            uint64_t ad = make_desc(smem_u32(dsm + buf*BUF_STRIDE));
            uint64_t bd = make_desc(smem_u32(dsm + buf*BUF_STRIDE + TILE_BYTES));
            #pragma unroll
            for (int k = 0; k < 4; k++)
                mma_f16_ss(tmem_ptr_s, ad + k*2, bd + k*2, IDESC_F16_N256,
                           (t == 0 && k == 0) ? 0u : 1u);
            tmem_commit(mb);
        }
    }
    mbar_wait(mb1, ph1);
    TC_FENCE_AFTER();
    const uint32_t tmem = tmem_ptr_s;

    {
        const int lg      = wid & 3;
        const uint32_t woff = ((uint32_t)lg) << 21;
        const int co      = lg*32 + (tid & 31);
        const int colbase = (wid >> 2) * 128;
        float* op = outR + (long long)b*OUT_BSTRIDE + co*HW + pc*256 + colbase;
        #pragma unroll
        for (int c = 0; c < 4; c++) {
            uint32_t r[32];
            LD_X32(r, tmem + colbase + c*32 + woff);
            TC_WAIT_LD();
            #pragma unroll
            for (int j = 0; j < 8; j++)
                ((float4*)(op + c*32))[j] = make_float4(
                    __uint_as_float(r[j*4+0]), __uint_as_float(r[j*4+1]),
                    __uint_as_float(r[j*4+2]), __uint_as_float(r[j*4+3]));
        }
        TC_FENCE_BEFORE();
    }
    __syncthreads();
    if (tid == 0) { mbar_inval(mb0); mbar_inval(mb1); mbar_inval(ab0); mbar_inval(ab1); }
    __syncthreads();
    if (wid == 0) TC_DEALLOC(tmem, 256);
#endif  // HAS_TC05
}

// ---------------------------------------------------------------------------
// max-pool term only, vectorized RMW into out (non-atomic; exclusive ownership)
// ---------------------------------------------------------------------------
__global__ __launch_bounds__(256) void k_maxp(
    const float* __restrict__ h0, int h0bs,
    const float* __restrict__ h1, int h1bs,
    float* __restrict__ outR, int eA, int eB)
{
    __shared__ __align__(16) float tl[8][34*36];
    const int b  = blockIdx.x >> 5;
    const int c0 = (blockIdx.x & 31) << 2;
    const int tid = threadIdx.x;

    const float4 ninf = make_float4(-INFINITY, -INFINITY, -INFINITY, -INFINITY);
    for (int i = tid; i < (8*34*36)/4; i += 256) ((float4*)tl)[i] = ninf;
    __syncthreads();
    // load 8 planes (2 edges x 4 ch), float4 over pixels
    for (int i4 = tid; i4 < 8*256; i4 += 256) {
        int e = i4 >> 10, ch = (i4 >> 8) & 3, p4 = i4 & 255;
        int pxi = p4 * 4;
        int y = pxi >> 5, x = pxi & 31;
        const float* hb = e ? (h1 + (long long)b*h1bs) : (h0 + (long long)b*h0bs);
        float4 v = *(const float4*)&hb[(c0+ch)*HW + pxi];
        float* d = &tl[e*4+ch][(y+1)*36 + x + 1];
        d[0] = v.x; d[1] = v.y; d[2] = v.z; d[3] = v.w;
    }
    __syncthreads();

    const float a4A = g_asoft[eA*5+4];
    const float a4B = g_asoft[eB*5+4];

    const int ch = tid >> 6;
    float* op = outR + (long long)b*OUT_BSTRIDE + (c0+ch)*HW;
    #pragma unroll
    for (int j = 0; j < 4; j++) {
        int p4  = (tid & 63) + j*64;      // 0..255
        int pxi = p4 * 4;
        int y   = pxi >> 5, x0 = pxi & 31;
        int base = (y+1)*36 + x0 + 1;
        float acc[4] = {0.f, 0.f, 0.f, 0.f};
        #pragma unroll
        for (int e = 0; e < 2; e++) {
            const float* tc = tl[e*4+ch];
            float a = e ? a4B : a4A;
            #pragma unroll
            for (int q = 0; q < 4; q++) {
                float mx = -INFINITY;
                #pragma unroll
                for (int dy = -1; dy <= 1; dy++)
                    #pragma unroll
                    for (int dx = -1; dx <= 1; dx++)
                        mx = fmaxf(mx, tc[base + q + dy*36 + dx]);
                acc[q] += a * mx;
            }
        }
        float4 cur = *(float4*)&op[pxi];
        cur.x += acc[0]; cur.y += acc[1]; cur.z += acc[2]; cur.w += acc[3];
        *(float4*)&op[pxi] = cur;
    }
}

// ---------------------------------------------------------------------------
__global__ void k_copy_skip(const float* __restrict__ skip,
                            float* __restrict__ out,
                            float* __restrict__ out2) {
    int i = blockIdx.x * 256 + threadIdx.x;
    if (i >= (BATCH*C*HW)/4) return;
    float4 v = ((const float4*)skip)[i];
    int pe = i * 4;
    int b  = pe >> 17;
    int r  = pe & (C*HW - 1);
    *(float4*)(out + (long long)b*OUT_BSTRIDE + 4*C*HW + r) = v;
    if (out2) ((float4*)out2)[i] = v;
}

// ---------------------------------------------------------------------------
static void launch_node(const float* h0, int h0bs, const float* h1, int h1bs,
                        float* outR, int eA, int eB) {
    k_node_mma<<<BATCH*4, 256, DSMEM_SZ>>>(h0, h0bs, h1, h1bs, outR, eA, eB);
    k_maxp    <<<BATCH*32, 256>>>         (h0, h0bs, h1, h1bs, outR, eA, eB);
}

extern "C" void kernel_launch(void* const* d_in, const int* in_sizes, int n_in,
                              void* d_out, int out_size) {
    const float* input0 = (const float*)d_in[0];
    const float* input1 = (const float*)d_in[1];
    const float* skip   = (const float*)d_in[2];
    const float* w_pre0 = (const float*)d_in[3];
    const float* w_pre1 = (const float*)d_in[4];
    const float* w3     = (const float*)d_in[5];
    const float* wd3    = (const float*)d_in[6];
    const float* alphas = (const float*)d_in[7];
    float* out = (float*)d_out;

    float *s0, *s1;
    cudaGetSymbolAddress((void**)&s0, g_s0);
    cudaGetSymbolAddress((void**)&s1, g_s1);

    cudaFuncSetAttribute(k_node_mma, cudaFuncAttributeMaxDynamicSharedMemorySize, DSMEM_SZ);
    cudaFuncSetAttribute(k_pre_mma,  cudaFuncAttributeMaxDynamicSharedMemorySize, DSMEM_PRE);

    long long concat_elems = (long long)BATCH*OUTC*HW;
    long long skip_elems   = (long long)BATCH*C*HW;
    float* out2 = nullptr;
    if ((long long)out_size >= concat_elems + skip_elems)
        out2 = out + concat_elems;

    k_prep<<<(2*KPAIR + 255)/256, 256>>>(alphas);
    k_combine_all<<<(EDGE_ELEMS + PRE_ELEMS + 255)/256, 256>>>(w3, wd3, w_pre0, w_pre1);
    k_pre_mma<<<2*BATCH*4, 256, DSMEM_PRE>>>(input0, input1, s0, s1);

    launch_node(s0, REG_STRIDE, s1, REG_STRIDE,                         out + 0*C*HW, 0, 1);
    k_copy_skip<<<((BATCH*C*HW/4) + 255)/256, 256>>>(skip, out, out2);
    launch_node(s1, REG_STRIDE, out + 0*C*HW, OUT_BSTRIDE,              out + 1*C*HW, 2, 3);
    launch_node(out + 0*C*HW, OUT_BSTRIDE, out + 1*C*HW, OUT_BSTRIDE,   out + 2*C*HW, 4, 5);
    launch_node(out + 1*C*HW, OUT_BSTRIDE, out + 2*C*HW, OUT_BSTRIDE,   out + 3*C*HW, 6, 7);
}

// round 17
// speedup vs baseline: 1.9576x; 1.0295x over previous
#include <cuda_runtime.h>
#include <math.h>
#include <stdint.h>

#define BATCH 64
#define C 128
#define HW 1024
#define OUTC 640
#define REG_STRIDE (C*HW)
#define OUT_BSTRIDE (OUTC*HW)

#define KPAIR 1152            // per edge: 64 ci-pairs * 18 taps
#define NST_EDGE 36           // super-tiles (32 pairs = 64 k) per edge
#define NTILES 72             // 2 edges
#define TILE_BYTES 16384      // A super-tile: 128 co x 64 k fp16 = 128B rows
#define BTILE_BYTES 32768     // B super-tile: 256 px x 64 k fp16 = 128B rows
#define BUF_STRIDE (TILE_BYTES + BTILE_BYTES)   // 49152
#define PLANE 432             // pair-plane: 12 rows * 36 cols (f16x2 per px)
#define RING_SLOTS 9
#define RING_BYTES (RING_SLOTS*PLANE*4)         // 15552
#define OFF_STAGE (2*BUF_STRIDE)                // 98304
#define DSMEM_SZ  (OFF_STAGE + RING_BYTES + 1024)   // 114880
#define DSMEM_PRE (2*BUF_STRIDE + 1024)             // 99328

#define EDGE_ELEMS (8*NST_EDGE*128*32)   // 1179648
#define PRE_ELEMS  (2*2*128*32)          // 16384

// hi edge-local PAIR-plane index touched by edge-local super-tile tl
#define HIP(tl) ((32*(tl) + 31) / 18)

// idesc kind::f16 (fp16): dtype=F32(bit4), atype=F16=0, btype=F16=0, N=256, M=128
#define IDESC_F16_N256 ((1u<<4)|(32u<<17)|(8u<<24))

#if defined(__CUDA_ARCH_FEAT_SM103_ALL) || defined(__CUDA_ARCH_FEAT_SM100_ALL) || \
    (defined(__CUDA_ARCH_SPECIFIC__) && (__CUDA_ARCH_SPECIFIC__ >= 1000))
#define HAS_TC05 1
#else
#define HAS_TC05 0
#endif

__device__ float g_s0[BATCH*C*HW];
__device__ float g_s1[BATCH*C*HW];
__device__ __align__(16) uint32_t gA[8*NST_EDGE*128*32];  // fp16 pairs, swizzled A super-tiles
__device__ __align__(16) uint32_t gApre[PRE_ELEMS];       // pre-conv A tiles
__device__ __align__(8) unsigned short g_kdec16[2*KPAIR]; // per-edge pair: slot*PLANE + spatial
__device__ float g_asoft[8*5];

// ---------------------------------------------------------------------------
__device__ __forceinline__ uint32_t smem_u32(const void* p) {
    uint32_t a;
    asm("{ .reg .u64 t; cvta.to.shared.u64 t, %1; cvt.u32.u64 %0, t; }" : "=r"(a) : "l"(p));
    return a;
}
#define SW128(o) ((o) ^ (((o) >> 3) & 0x70))
__device__ __forceinline__ uint32_t f16x2(float lo, float hi) {
    uint32_t u;
    asm("cvt.rn.f16x2.f32 %0, %1, %2;" : "=r"(u) : "f"(hi), "f"(lo));
    return u;
}

#if HAS_TC05
__device__ __forceinline__ uint32_t elect_one() {
    uint32_t p;
    asm volatile("{ .reg .pred p; elect.sync _|p, 0xFFFFFFFF; selp.b32 %0, 1, 0, p; }" : "=r"(p));
    return p;
}
__device__ __forceinline__ uint64_t make_desc(uint32_t addr) {
    const uint64_t base = (uint64_t(2) << 61) | (uint64_t(1) << 46)
                        | (uint64_t(64) << 32) | (uint64_t(1) << 16);
    return base | ((uint64_t)(addr >> 4) & 0x3FFF);
}
__device__ __forceinline__ void mma_f16_ss(uint32_t d, uint64_t ad, uint64_t bd,
                                           uint32_t idesc, uint32_t en) {
    asm volatile(
        "{\n\t.reg .pred p;\n\tsetp.ne.u32 p, %5, 0;\n\t"
        "tcgen05.mma.cta_group::1.kind::f16 [%0], %1, %2, %3, {%4, %4, %4, %4}, p;\n\t}"
        :: "r"(d), "l"(ad), "l"(bd), "r"(idesc), "r"(0u), "r"(en) : "memory");
}
__device__ __forceinline__ void mbar_init(uint32_t a, uint32_t cnt) {
    asm volatile("mbarrier.init.shared.b64 [%0], %1;" :: "r"(a), "r"(cnt) : "memory");
}
__device__ __forceinline__ void mbar_inval(uint32_t a) {
    asm volatile("mbarrier.inval.shared.b64 [%0];" :: "r"(a) : "memory");
}
__device__ __forceinline__ void mbar_wait(uint32_t a, uint32_t parity) {
    asm volatile(
        "{\n\t.reg .pred P;\n"
        "W_%=:\n\t"
        "mbarrier.try_wait.parity.acquire.cta.shared::cta.b64 P, [%0], %1, 0x989680;\n\t"
        "@P bra D_%=;\n\tbra W_%=;\nD_%=:\n\t}"
        :: "r"(a), "r"(parity) : "memory");
}
__device__ __forceinline__ void mbar_expect_tx(uint32_t a, uint32_t bytes) {
    asm volatile("mbarrier.arrive.expect_tx.shared.b64 _, [%0], %1;"
                 :: "r"(a), "r"(bytes) : "memory");
}
__device__ __forceinline__ void bulk_g2s(uint32_t dst, const void* src,
                                         uint32_t bytes, uint32_t mbar) {
    asm volatile(
        "cp.async.bulk.shared::cta.global.mbarrier::complete_tx::bytes [%0], [%1], %2, [%3];"
        :: "r"(dst), "l"(src), "r"(bytes), "r"(mbar) : "memory");
}
__device__ __forceinline__ void tmem_commit(uint32_t mbar) {
    asm volatile(
        "tcgen05.commit.cta_group::1.mbarrier::arrive::one.shared::cluster.b64 [%0];"
        :: "r"(mbar) : "memory");
}
#define TC_ALLOC(dst, n)   asm volatile("tcgen05.alloc.cta_group::1.sync.aligned.shared::cta.b32 [%0], %1;" :: "r"(dst), "r"(n) : "memory")
#define TC_DEALLOC(t, n)   asm volatile("tcgen05.dealloc.cta_group::1.sync.aligned.b32 %0, %1;" :: "r"(t), "r"(n))
#define TC_RELINQ()        asm volatile("tcgen05.relinquish_alloc_permit.cta_group::1.sync.aligned;")
#define TC_FENCE_AFTER()   asm volatile("tcgen05.fence::after_thread_sync;" ::: "memory")
#define TC_FENCE_BEFORE()  asm volatile("tcgen05.fence::before_thread_sync;" ::: "memory")
#define TC_WAIT_LD()       asm volatile("tcgen05.wait::ld.sync.aligned;" ::: "memory")
#define FENCE_ASYNC()      asm volatile("fence.proxy.async.shared::cta;" ::: "memory")

#define LD_X32(r, a) \
    asm volatile("tcgen05.ld.sync.aligned.32x32b.x32.b32 " \
        "{%0,%1,%2,%3,%4,%5,%6,%7,%8,%9,%10,%11,%12,%13,%14,%15," \
        "%16,%17,%18,%19,%20,%21,%22,%23,%24,%25,%26,%27,%28,%29,%30,%31}, [%32];" \
        : "=r"((r)[0]),"=r"((r)[1]),"=r"((r)[2]),"=r"((r)[3]), \
          "=r"((r)[4]),"=r"((r)[5]),"=r"((r)[6]),"=r"((r)[7]), \
          "=r"((r)[8]),"=r"((r)[9]),"=r"((r)[10]),"=r"((r)[11]), \
          "=r"((r)[12]),"=r"((r)[13]),"=r"((r)[14]),"=r"((r)[15]), \
          "=r"((r)[16]),"=r"((r)[17]),"=r"((r)[18]),"=r"((r)[19]), \
          "=r"((r)[20]),"=r"((r)[21]),"=r"((r)[22]),"=r"((r)[23]), \
          "=r"((r)[24]),"=r"((r)[25]),"=r"((r)[26]),"=r"((r)[27]), \
          "=r"((r)[28]),"=r"((r)[29]),"=r"((r)[30]),"=r"((r)[31]) \
        : "r"(a))
#endif  // HAS_TC05

// ---------------------------------------------------------------------------
// prep: softmax (block 0) + pair kdec table
// ---------------------------------------------------------------------------
__global__ void k_prep(const float* __restrict__ alphas) {
    if (blockIdx.x == 0 && threadIdx.x < 8) {
        int e = threadIdx.x;
        float m = -1e30f;
        #pragma unroll
        for (int i = 0; i < 5; i++) m = fmaxf(m, alphas[e*5+i]);
        float ex[5]; float s = 0.f;
        #pragma unroll
        for (int i = 0; i < 5; i++) { ex[i] = expf(alphas[e*5+i] - m); s += ex[i]; }
        float inv = 1.f / s;
        #pragma unroll
        for (int i = 0; i < 5; i++) g_asoft[e*5+i] = ex[i] * inv;
    }
    int idx = blockIdx.x * 256 + threadIdx.x;
    if (idx >= 2*KPAIR) return;
    int e  = idx / KPAIR;
    int p  = idx - e*KPAIR;
    int cp = p / 18, t = p - cp*18;
    int dy, dx;
    if (t < 9) { dy = t/3 - 1; dx = t%3 - 1; }
    else { int u = t - 9; dy = (u/3)*2 - 2; dx = (u%3)*2 - 2; }
    int slot = (e*64 + cp) % RING_SLOTS;
    g_kdec16[idx] = (unsigned short)(slot*PLANE + (dy+2)*36 + (dx+2));
}

// ---------------------------------------------------------------------------
// combine: edge A super-tiles in PAIRED K order + pre-conv A tiles
// ---------------------------------------------------------------------------
__global__ void k_combine_all(const float* __restrict__ w3, const float* __restrict__ wd3,
                              const float* __restrict__ w_pre0, const float* __restrict__ w_pre1) {
    int idx = blockIdx.x * 256 + threadIdx.x;
    if (idx < EDGE_ELEMS) {
        int kk = idx & 31;
        int r  = idx >> 5;
        int co = r & 127;
        int est = r >> 7;
        int e  = est / NST_EDGE, st = est - e*NST_EDGE;
        int p  = st*32 + kk;
        int cp = p / 18, t = p - cp*18;
        float a = (t < 9) ? g_asoft[e*5+1] : g_asoft[e*5+2];
        int tt  = (t < 9) ? t : t - 9;
        float v2[2];
        #pragma unroll
        for (int j = 0; j < 2; j++) {
            int ci = 2*cp + j;
            float val = a * ((t < 9 ? w3 : wd3)[((e*C + co)*C + ci)*9 + tt]);
            if (co == ci && t < 9) {
                val += g_asoft[e*5+3] * (1.f/9.f);
                if (t == 4) val += g_asoft[e*5+0];
            }
            v2[j] = val;
        }
        uint32_t off = SW128((uint32_t)(co*128 + kk*4));
        *(uint32_t*)((char*)gA + (size_t)est*TILE_BYTES + off) = f16x2(v2[0], v2[1]);
    } else {
        int p = idx - EDGE_ELEMS;
        if (p >= PRE_ELEMS) return;
        int kk = p & 31;
        int r  = p >> 5;
        int co = r & 127;
        int ist = r >> 7;
        const float* w = (ist >> 1) ? w_pre1 : w_pre0;
        int ci = (ist & 1)*64 + kk*2;
        uint32_t off = SW128((uint32_t)(co*128 + kk*4));
        *(uint32_t*)((char*)gApre + (size_t)ist*TILE_BYTES + off)
            = f16x2(w[co*C + ci], w[co*C + ci + 1]);
    }
}

// ---------------------------------------------------------------------------
// tensor-core 1x1 pre-conv, both inputs in one launch (grid 512).
// ---------------------------------------------------------------------------
__global__ __launch_bounds__(256) void k_pre_mma(const float* __restrict__ in0,
                                                 const float* __restrict__ in1,
                                                 float* __restrict__ outS0,
                                                 float* __restrict__ outS1)
{
#if HAS_TC05
    extern __shared__ char dsm_raw[];
    char* dsm = (char*)(((uintptr_t)dsm_raw + 1023) & ~(uintptr_t)1023);
    __shared__ __align__(16) uint64_t mbar[2];
    __shared__ __align__(16) uint64_t abar[2];
    __shared__ uint32_t tmem_ptr_s;

    const int tid = threadIdx.x;
    const int wid = tid >> 5;
    const int which = blockIdx.x >> 8;
    const int bidx  = blockIdx.x & 255;
    const int b   = bidx >> 2;
    const int pc  = bidx & 3;
    const float* in = which ? in1 : in0;
    float* outS    = which ? outS1 : outS0;

    if (wid == 0) {
        TC_ALLOC(smem_u32(&tmem_ptr_s), 256);
        TC_RELINQ();
    }
    if (tid == 0) {
        mbar_init(smem_u32(&mbar[0]), 1);
        mbar_init(smem_u32(&mbar[1]), 1);
        mbar_init(smem_u32(&abar[0]), 1);
        mbar_init(smem_u32(&abar[1]), 1);
    }
    const uint32_t mb0 = smem_u32(&mbar[0]);
    const uint32_t mb1 = smem_u32(&mbar[1]);
    const uint32_t ab0 = smem_u32(&abar[0]);
    const uint32_t ab1 = smem_u32(&abar[1]);
    const bool leader = (wid == 0) && elect_one();

    const float* inb = in + (long long)b*C*HW + pc*256;
    int aph0 = 0, aph1 = 0;
    __syncthreads();

    for (int t = 0; t < 2; t++) {
        const int buf = t;
        const uint32_t ab = buf ? ab1 : ab0;
        const uint32_t mb = buf ? mb1 : mb0;
        if (leader) {
            mbar_expect_tx(ab, TILE_BYTES);
            bulk_g2s(smem_u32(dsm + buf*BUF_STRIDE),
                     (const char*)gApre + (size_t)(which*2 + t)*TILE_BYTES,
                     TILE_BYTES, ab);
        }
        {
            char* Bd = dsm + buf*BUF_STRIDE + TILE_BYTES;
            const float* src = inb + (t*64)*HW;
            #pragma unroll
            for (int q = 0; q < 8; q++) {
                float v[8];
                #pragma unroll
                for (int j = 0; j < 8; j++)
                    v[j] = __ldg(&src[(q*8 + j)*HW + tid]);
                uint4 o;
                o.x = f16x2(v[0], v[1]); o.y = f16x2(v[2], v[3]);
                o.z = f16x2(v[4], v[5]); o.w = f16x2(v[6], v[7]);
                uint32_t off = SW128((uint32_t)(tid*128 + q*16));
                *(uint4*)(Bd + off) = o;
            }
        }
        __syncthreads();
        if (leader) {
            FENCE_ASYNC();
            if (buf) { mbar_wait(ab1, aph1); aph1 ^= 1; }
            else     { mbar_wait(ab0, aph0); aph0 ^= 1; }
            uint64_t ad = make_desc(smem_u32(dsm + buf*BUF_STRIDE));
            uint64_t bd = make_desc(smem_u32(dsm + buf*BUF_STRIDE + TILE_BYTES));
            #pragma unroll
            for (int k = 0; k < 4; k++)
                mma_f16_ss(tmem_ptr_s, ad + k*2, bd + k*2, IDESC_F16_N256,
                           (t == 0 && k == 0) ? 0u : 1u);
            tmem_commit(mb);
        }
    }
    mbar_wait(mb1, 0);
    TC_FENCE_AFTER();
    const uint32_t tmem = tmem_ptr_s;

    {
        const int lg      = wid & 3;
        const uint32_t woff = ((uint32_t)lg) << 21;
        const int co      = lg*32 + (tid & 31);
        const int colbase = (wid >> 2) * 128;
        float* op = outS + (long long)b*REG_STRIDE + co*HW + pc*256 + colbase;
        #pragma unroll
        for (int c = 0; c < 4; c++) {
            uint32_t r[32];
            LD_X32(r, tmem + colbase + c*32 + woff);
            TC_WAIT_LD();
            #pragma unroll
            for (int j = 0; j < 8; j++)
                ((float4*)(op + c*32))[j] = make_float4(
                    __uint_as_float(r[j*4+0]), __uint_as_float(r[j*4+1]),
                    __uint_as_float(r[j*4+2]), __uint_as_float(r[j*4+3]));
        }
        TC_FENCE_BEFORE();
    }
    __syncthreads();
    if (tid == 0) { mbar_inval(mb0); mbar_inval(mb1); mbar_inval(ab0); mbar_inval(ab1); }
    __syncthreads();
    if (wid == 0) TC_DEALLOC(tmem, 256);
#endif  // HAS_TC05
}

// ---------------------------------------------------------------------------
// tcgen05 fp16 node kernel: R13 core, 288 threads; warp 8 = dedicated leader
// (fence + A-wait + MMA issue + commit) so its serial chain overlaps the
// builders' next-tile work instead of stalling warp 0 at each barrier.
// ---------------------------------------------------------------------------
__global__ __launch_bounds__(288) void k_node_mma(
    const float* __restrict__ h0, int h0bs,
    const float* __restrict__ h1, int h1bs,
    float* __restrict__ outR, int eA, int eB)
{
#if HAS_TC05
    extern __shared__ char dsm_raw[];
    char* dsm = (char*)(((uintptr_t)dsm_raw + 1023) & ~(uintptr_t)1023);
    uint32_t* ring = (uint32_t*)(dsm + OFF_STAGE);   // [slot(9)][PLANE] f16x2
    __shared__ __align__(16) uint64_t mbar[2];
    __shared__ __align__(16) uint64_t abar[2];
    __shared__ uint32_t tmem_ptr_s;

    const int tid = threadIdx.x;
    const int wid = tid >> 5;
    const bool builder = (tid < 256);
    const int b   = blockIdx.x >> 2;
    const int pc  = blockIdx.x & 3;

    if (wid == 0) {
        TC_ALLOC(smem_u32(&tmem_ptr_s), 256);
        TC_RELINQ();
    }
    if (tid == 0) {
        mbar_init(smem_u32(&mbar[0]), 1);
        mbar_init(smem_u32(&mbar[1]), 1);
        mbar_init(smem_u32(&abar[0]), 1);
        mbar_init(smem_u32(&abar[1]), 1);
    }
    const uint32_t mb0 = smem_u32(&mbar[0]);
    const uint32_t mb1 = smem_u32(&mbar[1]);
    const uint32_t ab0 = smem_u32(&abar[0]);
    const uint32_t ab1 = smem_u32(&abar[1]);
    const bool leader = (wid == 8) && elect_one();

    const int px    = tid & 255;
    const int y0    = pc*8;
    const int tbase = (px >> 5)*36 + (px & 31);
    const float* hA = h0 + (long long)b * h0bs;
    const float* hB = h1 + (long long)b * h1bs;

    int go0, go1; bool va0, va1; const bool has1 = builder && (tid + 256) < PLANE;
    {
        int p = px, row = p/36, col = p - (p/36)*36;
        int gy = y0 + row - 2, gx = col - 2;
        va0 = ((unsigned)gy < 32u) && ((unsigned)gx < 32u);
        go0 = gy*32 + gx;
        p = px + 256; row = p/36; col = p - row*36;
        gy = y0 + row - 2; gx = col - 2;
        va1 = ((unsigned)gy < 32u) && ((unsigned)gx < 32u);
        go1 = gy*32 + gx;
    }
    float pv[2][2][2];              // [pair j][pixel][channel lo/hi]
    int   npl_lo = 0, npl_cnt = 0;  // edge-local pair-plane range
    int   npl_glob = 0;
    const float* npl_img = hA;

    auto calc_planes = [&](int tt) {
        int e = tt / NST_EDGE, tl = tt - e*NST_EDGE;
        npl_img = e ? hB : hA;
        int lo, hi = HIP(tl);
        if (tl == 0) lo = 0; else lo = HIP(tl - 1) + 1;
        npl_lo = lo; npl_cnt = hi - lo + 1;
        npl_glob = e*64 + lo;
    };
    auto stage_load = [&]() {
        #pragma unroll
        for (int j = 0; j < 2; j++) {
            if (j < npl_cnt) {
                const float* pl = npl_img + (size_t)(2*(npl_lo + j))*HW;
                pv[j][0][0] = va0 ? __ldg(&pl[go0]) : 0.f;
                pv[j][0][1] = va0 ? __ldg(&pl[HW + go0]) : 0.f;
                pv[j][1][0] = (has1 && va1) ? __ldg(&pl[go1]) : 0.f;
                pv[j][1][1] = (has1 && va1) ? __ldg(&pl[HW + go1]) : 0.f;
            }
        }
    };
    auto stage_store = [&]() {
        #pragma unroll
        for (int j = 0; j < 2; j++) {
            if (j < npl_cnt) {
                uint32_t* sl = ring + ((npl_glob + j) % RING_SLOTS)*PLANE;
                sl[px] = f16x2(pv[j][0][0], pv[j][0][1]);
                if (has1) sl[px + 256] = f16x2(pv[j][1][0], pv[j][1][1]);
            }
        }
    };

    int ph0 = 0, ph1 = 0;
    int aph0 = 0, aph1 = 0;

    if (builder) {
        calc_planes(0);
        stage_load();
        stage_store();
    }
    __syncthreads();

    for (int t = 0; t < NTILES; t++) {
        const int buf = t & 1;
        const uint32_t mb = buf ? mb1 : mb0;
        const uint32_t ab = buf ? ab1 : ab0;
        if (t >= 2) {
            if (buf) { mbar_wait(mb1, ph1); ph1 ^= 1; }
            else     { mbar_wait(mb0, ph0); ph0 ^= 1; }
        }
        const int e  = (t < NST_EDGE) ? 0 : 1;
        const int te = t - e*NST_EDGE;
        const int eg = e ? eB : eA;
        if (leader) {
            mbar_expect_tx(ab, TILE_BYTES);
            bulk_g2s(smem_u32(dsm + buf*BUF_STRIDE),
                     (const char*)gA + (size_t)(eg*NST_EDGE + te)*TILE_BYTES,
                     TILE_BYTES, ab);
        }
        if (builder) {
            if (t + 1 < NTILES) { calc_planes(t + 1); stage_load(); }
            else npl_cnt = 0;
            // ---- B build: 32 pair gathers (LDS.32, f16x2) -> 8 STS.128 ----
            {
                char* Bd = dsm + buf*BUF_STRIDE + TILE_BYTES;
                const ushort4* kdp = (const ushort4*)(g_kdec16 + e*KPAIR + te*32);
                #pragma unroll
                for (int q = 0; q < 8; q++) {
                    ushort4 k4 = __ldg(&kdp[q]);
                    uint4 o;
                    o.x = ring[k4.x + tbase];
                    o.y = ring[k4.y + tbase];
                    o.z = ring[k4.z + tbase];
                    o.w = ring[k4.w + tbase];
                    uint32_t off = SW128((uint32_t)(px*128 + q*16));
                    *(uint4*)(Bd + off) = o;
                }
            }
            stage_store();
        }
        __syncthreads();
        if (leader) {
            FENCE_ASYNC();
            if (buf) { mbar_wait(ab1, aph1); aph1 ^= 1; }
            else     { mbar_wait(ab0, aph0); aph0 ^= 1; }
            uint64_t ad = make_desc(smem_u32(dsm + buf*BUF_STRIDE));
            uint64_t bd = make_desc(smem_u32(dsm + buf*BUF_STRIDE + TILE_BYTES));
            #pragma unroll
            for (int k = 0; k < 4; k++)
                mma_f16_ss(tmem_ptr_s, ad + k*2, bd + k*2, IDESC_F16_N256,
                           (t == 0 && k == 0) ? 0u : 1u);
            tmem_commit(mb);
        }
    }
    mbar_wait(mb1, ph1);
    TC_FENCE_AFTER();
    const uint32_t tmem = tmem_ptr_s;

    if (builder) {
        const int lg      = wid & 3;
        const uint32_t woff = ((uint32_t)lg) << 21;
        const int co      = lg*32 + (tid & 31);
        const int colbase = (wid >> 2) * 128;
        float* op = outR + (long long)b*OUT_BSTRIDE + co*HW + pc*256 + colbase;
        #pragma unroll
        for (int c = 0; c < 4; c++) {
            uint32_t r[32];
            LD_X32(r, tmem + colbase + c*32 + woff);
            TC_WAIT_LD();
            #pragma unroll
            for (int j = 0; j < 8; j++)
                ((float4*)(op + c*32))[j] = make_float4(
                    __uint_as_float(r[j*4+0]), __uint_as_float(r[j*4+1]),
                    __uint_as_float(r[j*4+2]), __uint_as_float(r[j*4+3]));
        }
        TC_FENCE_BEFORE();
    }
    __syncthreads();
    if (tid == 0) { mbar_inval(mb0); mbar_inval(mb1); mbar_inval(ab0); mbar_inval(ab1); }
    __syncthreads();
    if (wid == 0) TC_DEALLOC(tmem, 256);
#endif  // HAS_TC05
}

// ---------------------------------------------------------------------------
// max-pool term only, vectorized RMW into out (non-atomic; exclusive ownership)
// ---------------------------------------------------------------------------
__global__ __launch_bounds__(256) void k_maxp(
    const float* __restrict__ h0, int h0bs,
    const float* __restrict__ h1, int h1bs,
    float* __restrict__ outR, int eA, int eB)
{
    __shared__ __align__(16) float tl[8][34*36];
    const int b  = blockIdx.x >> 5;
    const int c0 = (blockIdx.x & 31) << 2;
    const int tid = threadIdx.x;

    const float4 ninf = make_float4(-INFINITY, -INFINITY, -INFINITY, -INFINITY);
    for (int i = tid; i < (8*34*36)/4; i += 256) ((float4*)tl)[i] = ninf;
    __syncthreads();
    for (int i4 = tid; i4 < 8*256; i4 += 256) {
        int e = i4 >> 10, ch = (i4 >> 8) & 3, p4 = i4 & 255;
        int pxi = p4 * 4;
        int y = pxi >> 5, x = pxi & 31;
        const float* hb = e ? (h1 + (long long)b*h1bs) : (h0 + (long long)b*h0bs);
        float4 v = *(const float4*)&hb[(c0+ch)*HW + pxi];
        float* d = &tl[e*4+ch][(y+1)*36 + x + 1];
        d[0] = v.x; d[1] = v.y; d[2] = v.z; d[3] = v.w;
    }
    __syncthreads();

    const float a4A = g_asoft[eA*5+4];
    const float a4B = g_asoft[eB*5+4];

    const int ch = tid >> 6;
    float* op = outR + (long long)b*OUT_BSTRIDE + (c0+ch)*HW;
    #pragma unroll
    for (int j = 0; j < 4; j++) {
        int p4  = (tid & 63) + j*64;
        int pxi = p4 * 4;
        int y   = pxi >> 5, x0 = pxi & 31;
        int base = (y+1)*36 + x0 + 1;
        float acc[4] = {0.f, 0.f, 0.f, 0.f};
        #pragma unroll
        for (int e = 0; e < 2; e++) {
            const float* tc = tl[e*4+ch];
            float a = e ? a4B : a4A;
            #pragma unroll
            for (int q = 0; q < 4; q++) {
                float mx = -INFINITY;
                #pragma unroll
                for (int dy = -1; dy <= 1; dy++)
                    #pragma unroll
                    for (int dx = -1; dx <= 1; dx++)
                        mx = fmaxf(mx, tc[base + q + dy*36 + dx]);
                acc[q] += a * mx;
            }
        }
        float4 cur = *(float4*)&op[pxi];
        cur.x += acc[0]; cur.y += acc[1]; cur.z += acc[2]; cur.w += acc[3];
        *(float4*)&op[pxi] = cur;
    }
}

// ---------------------------------------------------------------------------
__global__ void k_copy_skip(const float* __restrict__ skip,
                            float* __restrict__ out,
                            float* __restrict__ out2) {
    int i = blockIdx.x * 256 + threadIdx.x;
    if (i >= (BATCH*C*HW)/4) return;
    float4 v = ((const float4*)skip)[i];
    int pe = i * 4;
    int b  = pe >> 17;
    int r  = pe & (C*HW - 1);
    *(float4*)(out + (long long)b*OUT_BSTRIDE + 4*C*HW + r) = v;
    if (out2) ((float4*)out2)[i] = v;
}

// ---------------------------------------------------------------------------
static void launch_node(const float* h0, int h0bs, const float* h1, int h1bs,
                        float* outR, int eA, int eB) {
    k_node_mma<<<BATCH*4, 288, DSMEM_SZ>>>(h0, h0bs, h1, h1bs, outR, eA, eB);
    k_maxp    <<<BATCH*32, 256>>>         (h0, h0bs, h1, h1bs, outR, eA, eB);
}

extern "C" void kernel_launch(void* const* d_in, const int* in_sizes, int n_in,
                              void* d_out, int out_size) {
    const float* input0 = (const float*)d_in[0];
    const float* input1 = (const float*)d_in[1];
    const float* skip   = (const float*)d_in[2];
    const float* w_pre0 = (const float*)d_in[3];
    const float* w_pre1 = (const float*)d_in[4];
    const float* w3     = (const float*)d_in[5];
    const float* wd3    = (const float*)d_in[6];
    const float* alphas = (const float*)d_in[7];
    float* out = (float*)d_out;

    float *s0, *s1;
    cudaGetSymbolAddress((void**)&s0, g_s0);
    cudaGetSymbolAddress((void**)&s1, g_s1);

    cudaFuncSetAttribute(k_node_mma, cudaFuncAttributeMaxDynamicSharedMemorySize, DSMEM_SZ);
    cudaFuncSetAttribute(k_pre_mma,  cudaFuncAttributeMaxDynamicSharedMemorySize, DSMEM_PRE);

    long long concat_elems = (long long)BATCH*OUTC*HW;
    long long skip_elems   = (long long)BATCH*C*HW;
    float* out2 = nullptr;
    if ((long long)out_size >= concat_elems + skip_elems)
        out2 = out + concat_elems;

    k_prep<<<(2*KPAIR + 255)/256, 256>>>(alphas);
    k_combine_all<<<(EDGE_ELEMS + PRE_ELEMS + 255)/256, 256>>>(w3, wd3, w_pre0, w_pre1);
    k_pre_mma<<<2*BATCH*4, 256, DSMEM_PRE>>>(input0, input1, s0, s1);

    launch_node(s0, REG_STRIDE, s1, REG_STRIDE,                         out + 0*C*HW, 0, 1);
    k_copy_skip<<<((BATCH*C*HW/4) + 255)/256, 256>>>(skip, out, out2);
    launch_node(s1, REG_STRIDE, out + 0*C*HW, OUT_BSTRIDE,              out + 1*C*HW, 2, 3);
    launch_node(out + 0*C*HW, OUT_BSTRIDE, out + 1*C*HW, OUT_BSTRIDE,   out + 2*C*HW, 4, 5);
    launch_node(out + 1*C*HW, OUT_BSTRIDE, out + 2*C*HW, OUT_BSTRIDE,   out + 3*C*HW, 6, 7);
}